// round 1
// baseline (speedup 1.0000x reference)
#include <cuda_runtime.h>
#include <cuda_bf16.h>

// Problem constants (fixed by the bench instance)
#define VSZ   32128
#define V4SZ  8032      // VSZ / 4
#define RIDX  512
#define LTOT  520
#define KD    8         // K = L - r

// Scratch (no cudaMalloc allowed)
__device__ float g_m[9];      // row max for rows 511..519
__device__ float g_s[9];      // sum exp(x - max)
__device__ int   g_amax[9];   // argmax index
__device__ int   g_nmatch;

// ---------------------------------------------------------------------------
// kernelA: per-row (rows 511..519) max / argmax / sum-exp. One block per row.
// ---------------------------------------------------------------------------
__global__ __launch_bounds__(256) void kernelA(const float* __restrict__ logits) {
    const int j = blockIdx.x;  // 0..8 -> logits row 511+j
    const float4* row = (const float4*)(logits + (size_t)(511 + j) * VSZ);
    const int tid = threadIdx.x;

    // pass 1: max + argmax (first-index tiebreak)
    float bm = -3.402823466e38f;
    int   bi = 0;
    for (int c = tid; c < V4SZ; c += 256) {
        float4 v = row[c];
        int base = 4 * c;
        if (v.x > bm) { bm = v.x; bi = base;     }
        if (v.y > bm) { bm = v.y; bi = base + 1; }
        if (v.z > bm) { bm = v.z; bi = base + 2; }
        if (v.w > bm) { bm = v.w; bi = base + 3; }
    }
    __shared__ float sm[256];
    __shared__ int   si[256];
    sm[tid] = bm; si[tid] = bi;
    __syncthreads();
    for (int off = 128; off > 0; off >>= 1) {
        if (tid < off) {
            float om = sm[tid + off]; int oi = si[tid + off];
            if (om > sm[tid] || (om == sm[tid] && oi < si[tid])) { sm[tid] = om; si[tid] = oi; }
        }
        __syncthreads();
    }
    const float M = sm[0];
    const int   A = si[0];

    // pass 2: sum exp(x - M) (row is hot in L1/L2)
    float s = 0.f;
    for (int c = tid; c < V4SZ; c += 256) {
        float4 v = row[c];
        s += __expf(v.x - M) + __expf(v.y - M) + __expf(v.z - M) + __expf(v.w - M);
    }
    __shared__ float ss[256];
    ss[tid] = s;
    __syncthreads();
    for (int off = 128; off > 0; off >>= 1) {
        if (tid < off) ss[tid] += ss[tid + off];
        __syncthreads();
    }
    if (tid == 0) { g_m[j] = M; g_s[j] = ss[0]; g_amax[j] = A; }
}

// ---------------------------------------------------------------------------
// kernelB: id-dtype detection, accept chain, n_match, id_res + n_match output.
// ---------------------------------------------------------------------------
__global__ __launch_bounds__(128) void kernelB(const float* __restrict__ logits,
                                               const float* __restrict__ probs,
                                               const void*  __restrict__ idsv,
                                               float* __restrict__ out,
                                               int out_size) {
    const int tid = threadIdx.x;
    __shared__ int s_nz;
    __shared__ int s_acc[KD];
    __shared__ int s_d[KD];
    if (tid == 0) s_nz = 0;
    __syncthreads();

    // dtype probe: int64 little-endian nonneg ids => all odd 32-bit words zero.
    // Probe stays within the first 520 words (safe for both int32 and int64 buffers).
    const int* w = (const int*)idsv;
    for (int i = 1 + 2 * tid; i < LTOT; i += 2 * 128)
        if (w[i] != 0) s_nz = 1;   // benign race
    __syncthreads();
    const bool is64 = (s_nz == 0);
    const long long* w64 = (const long long*)idsv;

    // id_res[0:512] = input_ids[0:512]
    for (int i = tid; i < RIDX; i += 128) {
        int idv = is64 ? (int)w64[i] : w[i];
        out[i] = (float)idv;
    }

    // accept[j], j = 0..7
    if (tid < KD) {
        int d = is64 ? (int)w64[RIDX + tid] : w[RIDX + tid];
        s_d[tid] = d;
        float tp = __expf(logits[(size_t)(511 + tid) * VSZ + d] - g_m[tid]) / g_s[tid];
        float pp = probs[(size_t)(511 + tid) * VSZ + d];
        int eq      = (g_amax[tid] == d);
        int lenient = (tp > pp * 0.5f);    // leniency = 2 (>1), pp/2 exact
        s_acc[tid] = eq | lenient;
    }
    __syncthreads();

    if (tid == 0) {
        int nm = 0;
        for (int j = 0; j < KD; j++) { if (s_acc[j]) nm++; else break; }
        for (int pos = 0; pos <= KD; pos++) {
            float v;
            if (pos < nm)       v = (float)s_d[pos];
            else if (pos == nm) v = (float)g_amax[pos];
            else                v = 0.f;
            out[RIDX + pos] = v;
        }
        out[out_size - 1] = (float)nm;
        g_nmatch = nm;
    }
}

// ---------------------------------------------------------------------------
// kernelC: big streaming assembly of prob_res (rows 0..519).
//   rows < 512: copy probs
//   rows 512..519 (j=row-512): softmax(logits row row-1) if j < n_match else 0
// Output base offset 521 is ==1 mod 4, so float4 loads + scalar stores.
// ---------------------------------------------------------------------------
__global__ __launch_bounds__(256) void kernelC(const float* __restrict__ probs,
                                               const float* __restrict__ logits,
                                               float* __restrict__ out) {
    const int row = blockIdx.y;
    const int c0  = blockIdx.x * 1024 + threadIdx.x;
    float* orow = out + 521 + (size_t)row * VSZ;

    if (row < RIDX) {
        const float4* p = (const float4*)(probs + (size_t)row * VSZ);
        #pragma unroll
        for (int k = 0; k < 4; k++) {
            int c = c0 + k * 256;
            if (c < V4SZ) {
                float4 v = p[c];
                float* o = orow + 4 * c;
                o[0] = v.x; o[1] = v.y; o[2] = v.z; o[3] = v.w;
            }
        }
    } else {
        const int j  = row - RIDX;
        const int nm = g_nmatch;
        if (j < nm) {
            const float M   = g_m[j];
            const float inv = 1.0f / g_s[j];
            const float4* p = (const float4*)(logits + (size_t)(row - 1) * VSZ);
            #pragma unroll
            for (int k = 0; k < 4; k++) {
                int c = c0 + k * 256;
                if (c < V4SZ) {
                    float4 v = p[c];
                    float* o = orow + 4 * c;
                    o[0] = __expf(v.x - M) * inv;
                    o[1] = __expf(v.y - M) * inv;
                    o[2] = __expf(v.z - M) * inv;
                    o[3] = __expf(v.w - M) * inv;
                }
            }
        } else {
            #pragma unroll
            for (int k = 0; k < 4; k++) {
                int c = c0 + k * 256;
                if (c < V4SZ) {
                    float* o = orow + 4 * c;
                    o[0] = 0.f; o[1] = 0.f; o[2] = 0.f; o[3] = 0.f;
                }
            }
        }
    }
}

// ---------------------------------------------------------------------------
extern "C" void kernel_launch(void* const* d_in, const int* in_sizes, int n_in,
                              void* d_out, int out_size) {
    const float* logits = (const float*)d_in[0];   // target_logits f32 (1,520,32128)
    const float* probs  = (const float*)d_in[1];   // probs         f32 (1,520,32128)
    const void*  ids    = d_in[2];                 // input_ids int32 or int64 (1,520)
    float* out = (float*)d_out;

    kernelA<<<9, 256>>>(logits);
    kernelB<<<1, 128>>>(logits, probs, ids, out, out_size);
    kernelC<<<dim3(8, 520), 256>>>(probs, logits, out);
}

// round 2
// speedup vs baseline: 1.2263x; 1.2263x over previous
#include <cuda_runtime.h>
#include <cuda_bf16.h>

// Problem constants (fixed by the bench instance)
#define VSZ   32128
#define V4SZ  8032      // VSZ / 4
#define RIDX  512
#define LTOT  520
#define KD    8         // K = L - r
#define NCH   16        // chunks per row for the parallel reduction
#define CH4   (V4SZ / NCH)   // 502 float4 per chunk

// Scratch (no cudaMalloc allowed)
__device__ float g_pm[9][NCH];   // partial max
__device__ float g_ps[9][NCH];   // partial sum exp(x - local max)
__device__ int   g_pa[9][NCH];   // partial argmax (global index, first occurrence)
__device__ float g_m[9];         // row max for rows 511..519
__device__ float g_s[9];         // sum exp(x - max)
__device__ int   g_amax[9];      // argmax index
__device__ int   g_nmatch;

// ---------------------------------------------------------------------------
// kernelA: partial max/argmax/sumexp. grid = (NCH, 9), one wave of 144 blocks.
// Single pass per chunk (online softmax partials).
// ---------------------------------------------------------------------------
__global__ __launch_bounds__(256) void kernelA(const float* __restrict__ logits) {
    const int j  = blockIdx.y;             // 0..8 -> logits row 511+j
    const int ch = blockIdx.x;             // 0..15
    const int tid = threadIdx.x;
    const float4* row = (const float4*)(logits + (size_t)(511 + j) * VSZ) + ch * CH4;

    float bm = -3.402823466e38f;
    int   bi = 0x7fffffff;
    float s  = 0.f;
    for (int c = tid; c < CH4; c += 256) {
        float4 v = row[c];
        int base = 4 * (ch * CH4 + c);
        // running max/argmax (first index) + online sum
        if (v.x > bm) { s *= __expf(bm - v.x); s += 1.f; bm = v.x; bi = base;     } else s += __expf(v.x - bm);
        if (v.y > bm) { s *= __expf(bm - v.y); s += 1.f; bm = v.y; bi = base + 1; } else s += __expf(v.y - bm);
        if (v.z > bm) { s *= __expf(bm - v.z); s += 1.f; bm = v.z; bi = base + 2; } else s += __expf(v.z - bm);
        if (v.w > bm) { s *= __expf(bm - v.w); s += 1.f; bm = v.w; bi = base + 3; } else s += __expf(v.w - bm);
    }

    __shared__ float sm[256], ss[256];
    __shared__ int   si[256];
    sm[tid] = bm; si[tid] = bi; ss[tid] = s;
    __syncthreads();
    for (int off = 128; off > 0; off >>= 1) {
        if (tid < off) {
            float om = sm[tid + off]; int oi = si[tid + off]; float os = ss[tid + off];
            float mm = sm[tid];       int mi = si[tid];       float ms = ss[tid];
            float M  = fmaxf(om, mm);
            ss[tid] = ms * __expf(mm - M) + os * __expf(om - M);
            if (om > mm || (om == mm && oi < mi)) { sm[tid] = om; si[tid] = oi; }
        }
        __syncthreads();
    }
    if (tid == 0) { g_pm[j][ch] = sm[0]; g_ps[j][ch] = ss[0]; g_pa[j][ch] = si[0]; }
}

// ---------------------------------------------------------------------------
// kernelB: combine partials (tid<9), then dtype probe, accept chain, n_match,
// id_res + n_match output.
// ---------------------------------------------------------------------------
__global__ __launch_bounds__(128) void kernelB(const float* __restrict__ logits,
                                               const float* __restrict__ probs,
                                               const void*  __restrict__ idsv,
                                               float* __restrict__ out,
                                               int out_size) {
    const int tid = threadIdx.x;
    __shared__ int s_nz;
    __shared__ int s_acc[KD];
    __shared__ int s_d[KD];
    if (tid == 0) s_nz = 0;

    // combine the NCH partials per row (sequential -> first-index tiebreak free)
    if (tid < 9) {
        float M = -3.402823466e38f;
        int   A = 0;
        #pragma unroll
        for (int c = 0; c < NCH; c++) {
            float pm = g_pm[tid][c];
            if (pm > M) { M = pm; A = g_pa[tid][c]; }
        }
        float S = 0.f;
        #pragma unroll
        for (int c = 0; c < NCH; c++)
            S += g_ps[tid][c] * __expf(g_pm[tid][c] - M);
        g_m[tid] = M; g_s[tid] = S; g_amax[tid] = A;
    }
    __syncthreads();

    // dtype probe: int64 little-endian nonneg ids => all odd 32-bit words zero.
    const int* w = (const int*)idsv;
    for (int i = 1 + 2 * tid; i < LTOT; i += 2 * 128)
        if (w[i] != 0) s_nz = 1;   // benign race
    __syncthreads();
    const bool is64 = (s_nz == 0);
    const long long* w64 = (const long long*)idsv;

    // id_res[0:512] = input_ids[0:512]
    for (int i = tid; i < RIDX; i += 128) {
        int idv = is64 ? (int)w64[i] : w[i];
        out[i] = (float)idv;
    }

    // accept[j], j = 0..7
    if (tid < KD) {
        int d = is64 ? (int)w64[RIDX + tid] : w[RIDX + tid];
        s_d[tid] = d;
        float tp = __expf(logits[(size_t)(511 + tid) * VSZ + d] - g_m[tid]) / g_s[tid];
        float pp = probs[(size_t)(511 + tid) * VSZ + d];
        int eq      = (g_amax[tid] == d);
        int lenient = (tp > pp * 0.5f);    // leniency = 2 (>1), pp/2 exact
        s_acc[tid] = eq | lenient;
    }
    __syncthreads();

    if (tid == 0) {
        int nm = 0;
        for (int j = 0; j < KD; j++) { if (s_acc[j]) nm++; else break; }
        for (int pos = 0; pos <= KD; pos++) {
            float v;
            if (pos < nm)       v = (float)s_d[pos];
            else if (pos == nm) v = (float)g_amax[pos];
            else                v = 0.f;
            out[RIDX + pos] = v;
        }
        out[out_size - 1] = (float)nm;
        g_nmatch = nm;
    }
}

// ---------------------------------------------------------------------------
// kernelC: big streaming assembly of prob_res (rows 0..519).
//   rows < 512: copy probs
//   rows 512..519 (j=row-512): softmax(logits row row-1) if j < n_match else 0
// Output base offset 521 is ==1 mod 4, so float4 loads + scalar stores.
// ---------------------------------------------------------------------------
__global__ __launch_bounds__(256) void kernelC(const float* __restrict__ probs,
                                               const float* __restrict__ logits,
                                               float* __restrict__ out) {
    const int row = blockIdx.y;
    const int c0  = blockIdx.x * 1024 + threadIdx.x;
    float* orow = out + 521 + (size_t)row * VSZ;

    if (row < RIDX) {
        const float4* p = (const float4*)(probs + (size_t)row * VSZ);
        #pragma unroll
        for (int k = 0; k < 4; k++) {
            int c = c0 + k * 256;
            if (c < V4SZ) {
                float4 v = p[c];
                float* o = orow + 4 * c;
                o[0] = v.x; o[1] = v.y; o[2] = v.z; o[3] = v.w;
            }
        }
    } else {
        const int j  = row - RIDX;
        const int nm = g_nmatch;
        if (j < nm) {
            const float M   = g_m[j];
            const float inv = 1.0f / g_s[j];
            const float4* p = (const float4*)(logits + (size_t)(row - 1) * VSZ);
            #pragma unroll
            for (int k = 0; k < 4; k++) {
                int c = c0 + k * 256;
                if (c < V4SZ) {
                    float4 v = p[c];
                    float* o = orow + 4 * c;
                    o[0] = __expf(v.x - M) * inv;
                    o[1] = __expf(v.y - M) * inv;
                    o[2] = __expf(v.z - M) * inv;
                    o[3] = __expf(v.w - M) * inv;
                }
            }
        } else {
            #pragma unroll
            for (int k = 0; k < 4; k++) {
                int c = c0 + k * 256;
                if (c < V4SZ) {
                    float* o = orow + 4 * c;
                    o[0] = 0.f; o[1] = 0.f; o[2] = 0.f; o[3] = 0.f;
                }
            }
        }
    }
}

// ---------------------------------------------------------------------------
extern "C" void kernel_launch(void* const* d_in, const int* in_sizes, int n_in,
                              void* d_out, int out_size) {
    const float* logits = (const float*)d_in[0];   // target_logits f32 (1,520,32128)
    const float* probs  = (const float*)d_in[1];   // probs         f32 (1,520,32128)
    const void*  ids    = d_in[2];                 // input_ids int32 or int64 (1,520)
    float* out = (float*)d_out;

    kernelA<<<dim3(NCH, 9), 256>>>(logits);
    kernelB<<<1, 128>>>(logits, probs, ids, out, out_size);
    kernelC<<<dim3(8, 520), 256>>>(probs, logits, out);
}